// round 6
// baseline (speedup 1.0000x reference)
#include <cuda_runtime.h>
#include <stdint.h>

// XNOR binarized linear, warp-broadcast popc, column-split + deep prefetch.
// y[n,o] = (256 - 2*popc(xbits[n] ^ wbits[o])) * scale[o]
//
// Block = 128 thr / 4 warps. Chunk = 64 rows.
//   warp = rwarp*? : (warp&1) selects row sub-chunk (32 rows),
//                    (warp>>1) selects column half (128 outputs).
// Each warp: ballots its rows' sign bits (full 256-elem row), holds 4 weight
// groups (32 regs) + scales, prefetches 2 rows ahead. No smem, no barriers.

constexpr int NROWS = 262144;
constexpr int DIM   = 256;
constexpr int WPR   = 8;

constexpr int CHUNK_ROWS = 64;
constexpr int NCHUNK     = NROWS / CHUNK_ROWS;   // 4096
constexpr int GRID       = 740;                  // 148 SMs x 5 blocks

__device__ uint32_t g_wbits[DIM * WPR];

// ---------------------------------------------------------------------------
// Pre-kernel: pack weight sign bits (one warp per output row).
// Word (h*4+c), bit L  <->  element h*128 + 4L + c. Matches x packing below.
// ---------------------------------------------------------------------------
__global__ void pack_w_kernel(const float* __restrict__ w) {
    int warp = (blockIdx.x * blockDim.x + threadIdx.x) >> 5;
    int lane = threadIdx.x & 31;
    if (warp >= DIM) return;
    const float4* row = reinterpret_cast<const float4*>(w) + (size_t)warp * (DIM / 4);
#pragma unroll
    for (int h = 0; h < 2; ++h) {
        float4 v = row[h * 32 + lane];
        uint32_t m0 = __ballot_sync(0xFFFFFFFFu, v.x < 0.0f);
        uint32_t m1 = __ballot_sync(0xFFFFFFFFu, v.y < 0.0f);
        uint32_t m2 = __ballot_sync(0xFFFFFFFFu, v.z < 0.0f);
        uint32_t m3 = __ballot_sync(0xFFFFFFFFu, v.w < 0.0f);
        if (lane == 0) {
            *reinterpret_cast<uint4*>(&g_wbits[warp * WPR + h * 4]) =
                make_uint4(m0, m1, m2, m3);
        }
    }
}

// ---------------------------------------------------------------------------
// Main kernel.
// ---------------------------------------------------------------------------
__global__ void __launch_bounds__(128, 5)
xnor_split_kernel(const float* __restrict__ x,
                  const float* __restrict__ scale,
                  float* __restrict__ out) {
    const int warp  = threadIdx.x >> 5;
    const int lane  = threadIdx.x & 31;
    const int rwarp = warp & 1;      // row sub-chunk (32 rows each)
    const int half  = warp >> 1;     // output-column half (128 cols each)

    // 4 weight groups for this lane: columns o = half*128 + j*32 + lane.
    uint4 wlo[4], whi[4];
    float S[4];
#pragma unroll
    for (int j = 0; j < 4; ++j) {
        int o = half * 128 + j * 32 + lane;
        wlo[j] = *reinterpret_cast<const uint4*>(&g_wbits[o * WPR]);
        whi[j] = *reinterpret_cast<const uint4*>(&g_wbits[o * WPR + 4]);
        S[j] = scale[o];
    }

    constexpr uint32_t MAGIC256 = 0x4B400000u + 256u;   // 2^23*1.5 + 256

    const float4* x4 = reinterpret_cast<const float4*>(x);

    for (int ch = blockIdx.x; ch < NCHUNK; ch += gridDim.x) {
        const int row0 = ch * CHUNK_ROWS + rwarp * 32;
        const float4* rp = x4 + (size_t)row0 * (DIM / 4);
        float* orow = out + (size_t)row0 * DIM + half * 128 + lane;

        // depth-2 prefetch: rows r (c), r+1 (d) in flight
        float4 c0 = rp[lane];       float4 c1 = rp[32 + lane];
        float4 d0 = rp[64 + lane];  float4 d1 = rp[96 + lane];

#pragma unroll 2
        for (int r = 0; r < 32; ++r) {
            // issue row r+2 (clamped)
            const int rn = (r + 2 < 32) ? r + 2 : 31;
            float4 e0 = rp[rn * 64 + lane];
            float4 e1 = rp[rn * 64 + 32 + lane];

            // ballot-transpose row r's sign bits (broadcast to all lanes)
            uint32_t b0 = __ballot_sync(0xFFFFFFFFu, c0.x < 0.0f);
            uint32_t b1 = __ballot_sync(0xFFFFFFFFu, c0.y < 0.0f);
            uint32_t b2 = __ballot_sync(0xFFFFFFFFu, c0.z < 0.0f);
            uint32_t b3 = __ballot_sync(0xFFFFFFFFu, c0.w < 0.0f);
            uint32_t b4 = __ballot_sync(0xFFFFFFFFu, c1.x < 0.0f);
            uint32_t b5 = __ballot_sync(0xFFFFFFFFu, c1.y < 0.0f);
            uint32_t b6 = __ballot_sync(0xFFFFFFFFu, c1.z < 0.0f);
            uint32_t b7 = __ballot_sync(0xFFFFFFFFu, c1.w < 0.0f);

            // 4 independent output-group chains
#pragma unroll
            for (int j = 0; j < 4; ++j) {
                int p = __popc(b0 ^ wlo[j].x) + __popc(b1 ^ wlo[j].y) +
                        __popc(b2 ^ wlo[j].z) + __popc(b3 ^ wlo[j].w) +
                        __popc(b4 ^ whi[j].x) + __popc(b5 ^ whi[j].y) +
                        __popc(b6 ^ whi[j].z) + __popc(b7 ^ whi[j].w);
                uint32_t t = MAGIC256 - 2u * (uint32_t)p;       // IMAD
                float fd = __uint_as_float(t) - 12582912.0f;    // exact int->f32
                orow[j * 32] = fd * S[j];                       // single rounding
            }

            c0 = d0; c1 = d1; d0 = e0; d1 = e1;
            orow += DIM;
        }
    }
}

// ---------------------------------------------------------------------------
// kernel_launch: d_in[0]=x [N,256] f32, d_in[1]=weight [256,256] f32,
//                d_in[2]=scale [1,256] f32; d_out = y [N,256] f32.
// ---------------------------------------------------------------------------
extern "C" void kernel_launch(void* const* d_in, const int* in_sizes, int n_in,
                              void* d_out, int out_size) {
    const float* x      = (const float*)d_in[0];
    const float* weight = (const float*)d_in[1];
    const float* scale  = (const float*)d_in[2];
    float* out          = (float*)d_out;
    (void)in_sizes; (void)n_in; (void)out_size;

    pack_w_kernel<<<32, 256>>>(weight);
    xnor_split_kernel<<<GRID, 128>>>(x, scale, out);
}